// round 12
// baseline (speedup 1.0000x reference)
#include <cuda_runtime.h>
#include <cuda_bf16.h>
#include <cstdint>
#include <cstddef>

// ---------------- problem constants ----------------
constexpr int B = 8;
constexpr int N = 2048;
constexpr int KNN = 20;
constexpr int BN_ = B * N;   // 16384 rows total

// ---------------- scratch (static device memory; no allocation APIs) -----
__device__ __align__(256) float g_dist[(size_t)B * N * N];
__device__ __align__(256) int   g_idx [(size_t)B * N * KNN];
__device__ __align__(256) float g_xcat[(size_t)B * N * 512];
__device__ __align__(256) float g_P   [(size_t)B * N * 256];
__device__ __align__(256) float g_Q   [(size_t)B * N * 256];
__device__ __align__(256) float g_wq  [256 * 128];
__device__ __align__(256) float g_nrm [(size_t)B * N];
__device__ __align__(256) float g_loc [(size_t)B * N * 512];
__device__ __align__(256) float g_emb [(size_t)B * N * 1024];
__device__ __align__(256) float g_glob[(size_t)B * 1024];
__device__ __align__(256) float g_gb  [(size_t)B * 256];
__device__ __align__(256) float g_h1  [(size_t)B * N * 256];
__device__ __align__(256) float g_h2  [(size_t)B * N * 256];

// ======================= helpers =======================
__device__ __forceinline__ uint32_t smem_u32(const void* p) {
    uint32_t a;
    asm("{ .reg .u64 t; cvta.to.shared.u64 t, %1; cvt.u32.u64 %0, t; }"
        : "=r"(a) : "l"(p));
    return a;
}

__device__ __forceinline__ void ldsm4(uint32_t* r, uint32_t addr) {
    asm volatile("ldmatrix.sync.aligned.m8n8.x4.shared.b16 {%0,%1,%2,%3}, [%4];"
                 : "=r"(r[0]), "=r"(r[1]), "=r"(r[2]), "=r"(r[3]) : "r"(addr));
}

__device__ __forceinline__ void mma16816(float* c, const uint32_t* a,
                                         uint32_t b0, uint32_t b1) {
    asm volatile(
        "mma.sync.aligned.m16n8k16.row.col.f32.bf16.bf16.f32 "
        "{%0,%1,%2,%3}, {%4,%5,%6,%7}, {%8,%9}, {%0,%1,%2,%3};"
        : "+f"(c[0]), "+f"(c[1]), "+f"(c[2]), "+f"(c[3])
        : "r"(a[0]), "r"(a[1]), "r"(a[2]), "r"(a[3]), "r"(b0), "r"(b1));
}

// split fp32 -> bf16 hi/lo pairs (packed bf16x2)
__device__ __forceinline__ void split4(float4 v, uint2& h, uint2& l) {
    __nv_bfloat162 ha, hb, la, lb;
    ha.x = __float2bfloat16(v.x); ha.y = __float2bfloat16(v.y);
    hb.x = __float2bfloat16(v.z); hb.y = __float2bfloat16(v.w);
    la.x = __float2bfloat16(v.x - __bfloat162float(ha.x));
    la.y = __float2bfloat16(v.y - __bfloat162float(ha.y));
    lb.x = __float2bfloat16(v.z - __bfloat162float(hb.x));
    lb.y = __float2bfloat16(v.w - __bfloat162float(hb.y));
    h.x = *reinterpret_cast<uint32_t*>(&ha);
    h.y = *reinterpret_cast<uint32_t*>(&hb);
    l.x = *reinterpret_cast<uint32_t*>(&la);
    l.y = *reinterpret_cast<uint32_t*>(&lb);
}

// ============ split-bf16 HMMA GEMM: Out[m,o] = sum_c A[m,c]*W[o,c] ========
// 128x128 tile per CTA, 8 warps (4 in M x 2 in N), warp tile 32x64.
// K multiple of 32; M, O multiples of 128.
// modes: 0 plain | 1 lrelu(acc*s+t) | 3 lrelu((acc+g[(m/nper)*O+o])*s+t)
//        | 4 g[m]+g[o]-2*acc (distance, per-batch g)
constexpr int TSTR = 80;                      // bytes per smem row (64 data + 16 pad)
constexpr int HT_TILE = 128 * TSTR;           // one plane: 10240 B
constexpr int HT_SMEM = 4 * HT_TILE;          // 40960 B
constexpr int ESTR = 68;                      // epilogue smem stride (floats)

__global__ __launch_bounds__(256)
void hgemm_k(const float* __restrict__ A, int lda, long bA,
             const float* __restrict__ W, int ldw, long bW,
             float* __restrict__ Out, int ldo, long bO,
             int K, int mode,
             const float* __restrict__ s, const float* __restrict__ t,
             const float* __restrict__ g, long bG, int nper)
{
    extern __shared__ char smem[];
    char* pAH = smem;
    char* pAL = smem + HT_TILE;
    char* pWH = smem + 2 * HT_TILE;
    char* pWL = smem + 3 * HT_TILE;
    const uint32_t sAH = smem_u32(pAH), sAL = smem_u32(pAL);
    const uint32_t sWH = smem_u32(pWH), sWL = smem_u32(pWL);

    const int tid = threadIdx.x, lane = tid & 31, wid = tid >> 5;
    const int m0 = blockIdx.x * 128, n0 = blockIdx.y * 128;
    const int bz = blockIdx.z;
    const float* Ab = A + (long)bz * bA;
    const float* Wb = W + (long)bz * bW;
    const int wm = wid & 3;       // m-block of 32
    const int wn = wid >> 2;      // n-block of 64

    float acc[2][8][4];
#pragma unroll
    for (int i = 0; i < 2; i++)
#pragma unroll
        for (int j = 0; j < 8; j++)
#pragma unroll
            for (int u = 0; u < 4; u++) acc[i][j][u] = 0.f;

    const uint32_t lrow  = lane & 15;
    const uint32_t lcolb = (lane >> 4) * 16;   // k8-half byte offset

    for (int k0 = 0; k0 < K; k0 += 32) {
        // ---- stage chunk: 128 rows x 32 floats for A and W, split hi/lo ----
#pragma unroll
        for (int r = 0; r < 4; r++) {
            int e   = tid + r * 256;
            int row = e >> 3;         // 0..127
            int q   = e & 7;          // float4 index 0..7
            int so  = row * TSTR + q * 8;
            float4 av = *(const float4*)(Ab + (long)(m0 + row) * lda + k0 + q * 4);
            float4 wv = *(const float4*)(Wb + (long)(n0 + row) * ldw + k0 + q * 4);
            uint2 h, l;
            split4(av, h, l);
            *(uint2*)(pAH + so) = h;
            *(uint2*)(pAL + so) = l;
            split4(wv, h, l);
            *(uint2*)(pWH + so) = h;
            *(uint2*)(pWL + so) = l;
        }
        __syncthreads();

#pragma unroll
        for (int ks = 0; ks < 2; ks++) {
            uint32_t ahi[2][4], alo[2][4];
            uint32_t bhi[4][4], blo[4][4];
            const uint32_t abase = (uint32_t)(wm * 32 + lrow) * TSTR + ks * 32 + lcolb;
#pragma unroll
            for (int mf = 0; mf < 2; mf++) {
                ldsm4(ahi[mf], sAH + abase + mf * 16 * TSTR);
                ldsm4(alo[mf], sAL + abase + mf * 16 * TSTR);
            }
            const uint32_t wbase = (uint32_t)(wn * 64 + lrow) * TSTR + ks * 32 + lcolb;
#pragma unroll
            for (int nt = 0; nt < 4; nt++) {
                ldsm4(bhi[nt], sWH + wbase + nt * 16 * TSTR);
                ldsm4(blo[nt], sWL + wbase + nt * 16 * TSTR);
            }
#pragma unroll
            for (int mf = 0; mf < 2; mf++)
#pragma unroll
                for (int nt = 0; nt < 4; nt++)
#pragma unroll
                    for (int h = 0; h < 2; h++) {
                        float* c = acc[mf][nt * 2 + h];
                        mma16816(c, ahi[mf], bhi[nt][h], bhi[nt][h + 2]);
                        mma16816(c, ahi[mf], blo[nt][h], blo[nt][h + 2]);
                        mma16816(c, alo[mf], bhi[nt][h], bhi[nt][h + 2]);
                    }
        }
        __syncthreads();
    }

    // ---- epilogue: fused ops in registers ----
    const int tig = lane & 3, grp = lane >> 2;
    const int O = gridDim.y * 128;
    const float* gB = g + (long)bz * bG;

#pragma unroll
    for (int mf = 0; mf < 2; mf++) {
        const int mA = m0 + wm * 32 + mf * 16 + grp;   // rows mA and mA+8
#pragma unroll
        for (int nf = 0; nf < 8; nf++) {
            const int o = n0 + wn * 64 + nf * 8 + tig * 2;
            float* v = acc[mf][nf];
            if (mode == 1) {
                float s0 = s[o], s1 = s[o + 1], t0 = t[o], t1 = t[o + 1];
                v[0] = fmaf(v[0], s0, t0); v[1] = fmaf(v[1], s1, t1);
                v[2] = fmaf(v[2], s0, t0); v[3] = fmaf(v[3], s1, t1);
#pragma unroll
                for (int u = 0; u < 4; u++) v[u] = v[u] >= 0.f ? v[u] : 0.2f * v[u];
            } else if (mode == 3) {
                int g0 = (mA / nper) * O, g1 = ((mA + 8) / nper) * O;
                float s0 = s[o], s1 = s[o + 1], t0 = t[o], t1 = t[o + 1];
                v[0] = fmaf(v[0] + g[g0 + o],     s0, t0);
                v[1] = fmaf(v[1] + g[g0 + o + 1], s1, t1);
                v[2] = fmaf(v[2] + g[g1 + o],     s0, t0);
                v[3] = fmaf(v[3] + g[g1 + o + 1], s1, t1);
#pragma unroll
                for (int u = 0; u < 4; u++) v[u] = v[u] >= 0.f ? v[u] : 0.2f * v[u];
            } else if (mode == 4) {
                float gm0 = gB[mA], gm1 = gB[mA + 8];
                float gn0 = gB[o], gn1 = gB[o + 1];
                v[0] = gm0 + gn0 - 2.f * v[0];
                v[1] = gm0 + gn1 - 2.f * v[1];
                v[2] = gm1 + gn0 - 2.f * v[2];
                v[3] = gm1 + gn1 - 2.f * v[3];
            }
        }
    }

    // ---- staged coalesced stores: two passes of 128x64 half-tiles ----
    float* smf = (float*)smem;      // 128 x ESTR floats = 34816 B <= 40960
    float* obase = Out + (long)bz * bO + (long)m0 * ldo + n0;
#pragma unroll
    for (int p = 0; p < 2; p++) {
        __syncthreads();
        if (wn == p) {
            const int r0 = wm * 32 + grp;
#pragma unroll
            for (int mf = 0; mf < 2; mf++) {
#pragma unroll
                for (int nf = 0; nf < 8; nf++) {
                    const int cc = nf * 8 + tig * 2;
                    float* v = acc[mf][nf];
                    *(float2*)&smf[(r0 + mf * 16)     * ESTR + cc] = make_float2(v[0], v[1]);
                    *(float2*)&smf[(r0 + mf * 16 + 8) * ESTR + cc] = make_float2(v[2], v[3]);
                }
            }
        }
        __syncthreads();
#pragma unroll
        for (int it = 0; it < 8; it++) {
            int e = tid + it * 256;          // 0..2047
            int row = e >> 4, q = e & 15;
            float4 val = *(float4*)&smf[row * ESTR + q * 4];
            *(float4*)(obase + (long)row * ldo + p * 64 + q * 4) = val;
        }
    }
}

// ======================= fp32 SGEMM (odd shapes), batched =================
constexpr int BM = 128, BNt = 128, BK = 8;

__global__ __launch_bounds__(256, 2)
void sgemm_k(const float* __restrict__ A, int lda, long bA,
             const float* __restrict__ W, int ldw, int wcol, long bW,
             float* __restrict__ Out, int ldo, long bO,
             int M, int C, int O, int mode,
             const float* __restrict__ s, const float* __restrict__ t,
             const float* __restrict__ g, long bGs, int nper)
{
    __shared__ float As[BK][BM + 4];
    __shared__ float Ws[BK][BNt + 4];

    const int tid = threadIdx.x;
    const int tx = tid & 15;
    const int ty = tid >> 4;
    const int m0 = blockIdx.x * BM;
    const int n0 = blockIdx.y * BNt;
    const int bz = blockIdx.z;
    const float* Ab = A + (long)bz * bA;
    const float* Wb = W + (long)bz * bW;

    float acc[8][8];
#pragma unroll
    for (int i = 0; i < 8; i++)
#pragma unroll
        for (int j = 0; j < 8; j++) acc[i][j] = 0.f;

    for (int k0 = 0; k0 < C; k0 += BK) {
#pragma unroll
        for (int r = 0; r < 4; r++) {
            int e  = tid + r * 256;
            int mm = e >> 3;
            int kk = e & 7;
            int gk = k0 + kk;
            int gm = m0 + mm;
            As[kk][mm] = (gm < M && gk < C) ? Ab[(size_t)gm * lda + gk] : 0.f;
            int gn = n0 + mm;
            Ws[kk][mm] = (gn < O && gk < C) ? Wb[(size_t)gn * ldw + wcol + gk] : 0.f;
        }
        __syncthreads();

#pragma unroll
        for (int kk = 0; kk < BK; kk++) {
            float a[8], bb[8];
#pragma unroll
            for (int i = 0; i < 8; i++) a[i]  = As[kk][ty + 16 * i];
#pragma unroll
            for (int j = 0; j < 8; j++) bb[j] = Ws[kk][tx + 16 * j];
#pragma unroll
            for (int i = 0; i < 8; i++)
#pragma unroll
                for (int j = 0; j < 8; j++)
                    acc[i][j] = fmaf(a[i], bb[j], acc[i][j]);
        }
        __syncthreads();
    }

    const float* gb = g + (long)bz * bGs;
#pragma unroll
    for (int i = 0; i < 8; i++) {
        int m = m0 + ty + 16 * i;
        if (m >= M) continue;
#pragma unroll
        for (int j = 0; j < 8; j++) {
            int o = n0 + tx + 16 * j;
            if (o >= O) continue;
            float v = acc[i][j];
            if (mode == 1) {
                v = fmaf(v, s[o], t[o]);
                v = v >= 0.f ? v : 0.2f * v;
            } else if (mode == 2) {
                v += s[o];
            } else if (mode == 3) {
                v += gb[(m / nper) * O + o];
                v = fmaf(v, s[o], t[o]);
                v = v >= 0.f ? v : 0.2f * v;
            } else if (mode == 4) {
                v = gb[m] + gb[o] - 2.f * v;
            }
            Out[(long)bz * bO + (size_t)m * ldo + o] = v;
        }
    }
}

// ---------------- squared norms ----------------
__global__ void norms_k(const float* __restrict__ X, int lda, int C,
                        float* __restrict__ out, int M)
{
    int m = blockIdx.x * blockDim.x + threadIdx.x;
    if (m >= M) return;
    const float* p = X + (size_t)m * lda;
    float acc = 0.f;
    for (int c = 0; c < C; c++) acc = fmaf(p[c], p[c], acc);
    out[m] = acc;
}

// ---------------- top-k (k=20 smallest per row) -------------------------
// 8 warps x 256 elements each; per-warp register top-20, then 1-warp merge.
__global__ __launch_bounds__(256)
void topk_k(const float* __restrict__ D, int* __restrict__ idx)
{
    const int row = blockIdx.x;              // b*N + i ; D row offset row*N
    const float* d = D + (size_t)row * N;
    const int lane = threadIdx.x & 31, w = threadIdx.x >> 5;
    const int base = w * 256;

    float v[8];
#pragma unroll
    for (int it = 0; it < 8; it++) v[it] = d[base + it * 32 + lane];

    __shared__ float cval[160];
    __shared__ int   cidx[160];

    for (int kk = 0; kk < KNN; kk++) {
        float bv = v[0]; int slot = 0;
#pragma unroll
        for (int it = 1; it < 8; it++)
            if (v[it] < bv) { bv = v[it]; slot = it; }
        int bi = base + slot * 32 + lane;
#pragma unroll
        for (int off = 16; off; off >>= 1) {
            float ov = __shfl_xor_sync(0xffffffffu, bv, off);
            int   oi = __shfl_xor_sync(0xffffffffu, bi, off);
            if (ov < bv || (ov == bv && oi < bi)) { bv = ov; bi = oi; }
        }
        if (lane == 0) { cval[w * 20 + kk] = bv; cidx[w * 20 + kk] = bi; }
        int lj = bi - base;
        if ((lj & 31) == lane) v[lj >> 5] = 3.4e38f;
    }
    __syncthreads();

    if (w == 0) {
        float cv[5]; int ci[5];
#pragma unroll
        for (int it = 0; it < 5; it++) {
            int p = lane + it * 32;
            cv[it] = cval[p]; ci[it] = cidx[p];
        }
        for (int kk = 0; kk < KNN; kk++) {
            float bv = cv[0]; int bi = ci[0];
#pragma unroll
            for (int it = 1; it < 5; it++)
                if (cv[it] < bv || (cv[it] == bv && ci[it] < bi)) { bv = cv[it]; bi = ci[it]; }
#pragma unroll
            for (int off = 16; off; off >>= 1) {
                float ov = __shfl_xor_sync(0xffffffffu, bv, off);
                int   oi = __shfl_xor_sync(0xffffffffu, bi, off);
                if (ov < bv || (ov == bv && oi < bi)) { bv = ov; bi = oi; }
            }
            if (lane == 0) idx[(size_t)row * KNN + kk] = bi;
#pragma unroll
            for (int it = 0; it < 5; it++)
                if (ci[it] == bi) cv[it] = 3.4e38f;
        }
    }
}

// ---------------- weight diff: wq = w[:,C:2C] - w[:,0:C] ----------------
__global__ void wdiff_k(const float* __restrict__ w, int C, int O,
                        float* __restrict__ wq)
{
    int e = blockIdx.x * blockDim.x + threadIdx.x;
    if (e >= O * C) return;
    int o = e / C, c = e % C;
    wq[e] = w[(size_t)o * 2 * C + C + c] - w[(size_t)o * 2 * C + c];
}

// ---------------- edgeconv gather + lrelu + max over k ----------------
__global__ __launch_bounds__(256)
void edge_max_k(const float* __restrict__ P,
                const float* __restrict__ Q,
                const int* __restrict__ idx,
                const float* __restrict__ s,
                const float* __restrict__ t,
                float* __restrict__ out, int O, int choff)
{
    const int rpb = 256 / O;
    const int sub = threadIdx.x / O;
    const int o   = threadIdx.x - sub * O;
    const int row = blockIdx.x * rpb + sub;
    const int b   = row >> 11;
    const int* ip = idx + (size_t)row * KNN;

    const float q  = Q[(size_t)row * O + o];
    const float ss = s[o], tt = t[o];
    float m = -3.4e38f;
#pragma unroll
    for (int kk = 0; kk < KNN; kk++) {
        int j = ip[kk];
        float p = P[((size_t)(b * N + j)) * O + o];
        float v = fmaf(p + q, ss, tt);
        v = v >= 0.f ? v : 0.2f * v;
        m = fmaxf(m, v);
    }
    out[(size_t)row * 512 + choff + o] = m;
}

// ---------------- global max over N of x_emb ----------------
__global__ void gmax_k(const float* __restrict__ emb, float* __restrict__ glob)
{
    const int b = blockIdx.x;
    const int o = blockIdx.y * 256 + threadIdx.x;
    const float* p = emb + (size_t)b * N * 1024 + o;
    float m = -3.4e38f;
#pragma unroll 8
    for (int n = 0; n < N; n++) m = fmaxf(m, p[(size_t)n << 10]);
    glob[b * 1024 + o] = m;
}

// ---------------- host orchestration ----------------
static inline void run_sgemm(const float* A, int lda, const float* W, int ldw,
                             int wcol, float* Out, int ldo, int M, int C, int O,
                             int mode, const float* s, const float* t,
                             const float* g, int nper,
                             long bA = 0, long bW = 0, long bO = 0, long bG = 0,
                             int nbatch = 1)
{
    dim3 grid((M + BM - 1) / BM, (O + BNt - 1) / BNt, nbatch);
    sgemm_k<<<grid, 256>>>(A, lda, bA, W, ldw, wcol, bW, Out, ldo, bO,
                           M, C, O, mode, s, t, g, bG, nper);
}

static inline void run_tc(const float* A, int lda, long bA,
                          const float* W, int ldw, long bW,
                          float* Out, int ldo, long bO,
                          int M, int K, int O, int nbatch, int mode,
                          const float* s, const float* t,
                          const float* g, long bG, int nper)
{
    dim3 grid(M / 128, O / 128, nbatch);
    hgemm_k<<<grid, 256, HT_SMEM>>>(A, lda, bA, W, ldw, bW, Out, ldo, bO,
                                    K, mode, s, t, g, bG, nper);
}

extern "C" void kernel_launch(void* const* d_in, const int* in_sizes, int n_in,
                              void* d_out, int out_size)
{
    (void)in_sizes; (void)n_in; (void)out_size;
    cudaFuncSetAttribute(hgemm_k, cudaFuncAttributeMaxDynamicSharedMemorySize, HT_SMEM);

    const float* xyz   = (const float*)d_in[0];
    const float* ec1_w = (const float*)d_in[1];
    const float* ec1_s = (const float*)d_in[2];
    const float* ec1_t = (const float*)d_in[3];
    const float* ec2_w = (const float*)d_in[4];
    const float* ec2_s = (const float*)d_in[5];
    const float* ec2_t = (const float*)d_in[6];
    const float* ec3_w = (const float*)d_in[7];
    const float* ec3_s = (const float*)d_in[8];
    const float* ec3_t = (const float*)d_in[9];
    const float* ec4_w = (const float*)d_in[10];
    const float* ec4_s = (const float*)d_in[11];
    const float* ec4_t = (const float*)d_in[12];
    const float* fuse_w = (const float*)d_in[13];
    const float* fuse_s = (const float*)d_in[14];
    const float* fuse_t = (const float*)d_in[15];
    const float* emb_w = (const float*)d_in[16];
    const float* emb_s = (const float*)d_in[17];
    const float* emb_t = (const float*)d_in[18];
    const float* h1_w  = (const float*)d_in[19];
    const float* h1_s  = (const float*)d_in[20];
    const float* h1_t  = (const float*)d_in[21];
    const float* h2_w  = (const float*)d_in[22];
    const float* h2_s  = (const float*)d_in[23];
    const float* h2_t  = (const float*)d_in[24];
    const float* h3_w  = (const float*)d_in[25];
    const float* h3_b  = (const float*)d_in[26];
    float* out = (float*)d_out;

    float *dist, *xcat, *P, *Q, *wq, *nrm, *loc, *emb, *glob, *gb, *h1, *h2;
    int* idx;
    cudaGetSymbolAddress((void**)&dist, g_dist);
    cudaGetSymbolAddress((void**)&idx,  g_idx);
    cudaGetSymbolAddress((void**)&xcat, g_xcat);
    cudaGetSymbolAddress((void**)&P,    g_P);
    cudaGetSymbolAddress((void**)&Q,    g_Q);
    cudaGetSymbolAddress((void**)&wq,   g_wq);
    cudaGetSymbolAddress((void**)&nrm,  g_nrm);
    cudaGetSymbolAddress((void**)&loc,  g_loc);
    cudaGetSymbolAddress((void**)&emb,  g_emb);
    cudaGetSymbolAddress((void**)&glob, g_glob);
    cudaGetSymbolAddress((void**)&gb,   g_gb);
    cudaGetSymbolAddress((void**)&h1,   g_h1);
    cudaGetSymbolAddress((void**)&h2,   g_h2);

    // ---------- layer 1 (C=3: fp32 path; batched dist) ----------
    norms_k<<<(BN_ + 255) / 256, 256>>>(xyz, 3, 3, nrm, BN_);
    run_sgemm(xyz, 3, xyz, 3, 0, dist, N, N, 3, N, 4, nullptr, nullptr, nrm, 0,
              (long)N * 3, (long)N * 3, (long)N * N, N, B);
    topk_k<<<BN_, 256>>>(dist, idx);
    wdiff_k<<<(64 * 3 + 255) / 256, 256>>>(ec1_w, 3, 64, wq);
    run_sgemm(xyz, 3, ec1_w, 6, 0, P, 64, BN_, 3, 64, 0, nullptr, nullptr, nullptr, 0);
    run_sgemm(xyz, 3, wq,    3, 0, Q, 64, BN_, 3, 64, 0, nullptr, nullptr, nullptr, 0);
    edge_max_k<<<BN_ / 4, 256>>>(P, Q, idx, ec1_s, ec1_t, xcat, 64, 0);

    // ---------- layer 2 (C=64, O=64: HMMA dist, fp32 P/Q) ----------
    {
        const float* X = xcat;  // lda 512
        norms_k<<<(BN_ + 255) / 256, 256>>>(X, 512, 64, nrm, BN_);
        run_tc(X, 512, (long)N * 512, X, 512, (long)N * 512,
               dist, N, (long)N * N, N, 64, N, B, 4,
               nullptr, nullptr, nrm, N, 0);
        topk_k<<<BN_, 256>>>(dist, idx);
        wdiff_k<<<(64 * 64 + 255) / 256, 256>>>(ec2_w, 64, 64, wq);
        run_sgemm(X, 512, ec2_w, 128, 0, P, 64, BN_, 64, 64, 0, nullptr, nullptr, nullptr, 0);
        run_sgemm(X, 512, wq,    64,  0, Q, 64, BN_, 64, 64, 0, nullptr, nullptr, nullptr, 0);
        edge_max_k<<<BN_ / 4, 256>>>(P, Q, idx, ec2_s, ec2_t, xcat, 64, 64);
    }

    // ---------- layer 3 (C=64, O=128: HMMA) ----------
    {
        const float* X = xcat + 64;
        norms_k<<<(BN_ + 255) / 256, 256>>>(X, 512, 64, nrm, BN_);
        run_tc(X, 512, (long)N * 512, X, 512, (long)N * 512,
               dist, N, (long)N * N, N, 64, N, B, 4,
               nullptr, nullptr, nrm, N, 0);
        topk_k<<<BN_, 256>>>(dist, idx);
        wdiff_k<<<(128 * 64 + 255) / 256, 256>>>(ec3_w, 64, 128, wq);
        run_tc(X, 512, 0, ec3_w, 128, 0, P, 128, 0, BN_, 64, 128, 1, 0,
               nullptr, nullptr, nullptr, 0, 0);
        run_tc(X, 512, 0, wq, 64, 0, Q, 128, 0, BN_, 64, 128, 1, 0,
               nullptr, nullptr, nullptr, 0, 0);
        edge_max_k<<<BN_ / 2, 256>>>(P, Q, idx, ec3_s, ec3_t, xcat, 128, 128);
    }

    // ---------- layer 4 (C=128, O=256: HMMA) ----------
    {
        const float* X = xcat + 128;
        norms_k<<<(BN_ + 255) / 256, 256>>>(X, 512, 128, nrm, BN_);
        run_tc(X, 512, (long)N * 512, X, 512, (long)N * 512,
               dist, N, (long)N * N, N, 128, N, B, 4,
               nullptr, nullptr, nrm, N, 0);
        topk_k<<<BN_, 256>>>(dist, idx);
        wdiff_k<<<(256 * 128 + 255) / 256, 256>>>(ec4_w, 128, 256, wq);
        run_tc(X, 512, 0, ec4_w, 256, 0, P, 256, 0, BN_, 128, 256, 1, 0,
               nullptr, nullptr, nullptr, 0, 0);
        run_tc(X, 512, 0, wq, 128, 0, Q, 256, 0, BN_, 128, 256, 1, 0,
               nullptr, nullptr, nullptr, 0, 0);
        edge_max_k<<<BN_, 256>>>(P, Q, idx, ec4_s, ec4_t, xcat, 256, 256);
    }

    // fuse: 512 -> 512 (HMMA)
    run_tc(xcat, 512, 0, fuse_w, 512, 0, loc, 512, 0, BN_, 512, 512, 1, 1,
           fuse_s, fuse_t, nullptr, 0, 0);
    // emb: 512 -> 1024 (HMMA), then global max over N
    run_tc(loc, 512, 0, emb_w, 512, 0, emb, 1024, 0, BN_, 512, 1024, 1, 1,
           emb_s, emb_t, nullptr, 0, 0);
    gmax_k<<<dim3(B, 4), 256>>>(emb, glob);
    // gb[b,o] = glob[b] @ h1_w[o, 512:1536]  (tiny: fp32)
    run_sgemm(glob, 1024, h1_w, 1536, 512, gb, 256, B, 1024, 256, 0,
              nullptr, nullptr, nullptr, 0);
    // h1 = lrelu((loc @ h1_w[:, :512]^T + gb[b]) * s + t)  (HMMA, mode 3)
    run_tc(loc, 512, 0, h1_w, 1536, 0, h1, 256, 0, BN_, 512, 256, 1, 3,
           h1_s, h1_t, gb, 0, N);
    // h2 (HMMA)
    run_tc(h1, 256, 0, h2_w, 256, 0, h2, 256, 0, BN_, 256, 256, 1, 1,
           h2_s, h2_t, nullptr, 0, 0);
    // logits = h2 @ h3_w^T + b (O=13: fp32)
    run_sgemm(h2, 256, h3_w, 256, 0, out, 13, BN_, 256, 13, 2,
              h3_b, nullptr, nullptr, 0);
}

// round 13
// speedup vs baseline: 1.0949x; 1.0949x over previous
#include <cuda_runtime.h>
#include <cuda_bf16.h>
#include <cstdint>
#include <cstddef>

// ---------------- problem constants ----------------
constexpr int B = 8;
constexpr int N = 2048;
constexpr int KNN = 20;
constexpr int BN_ = B * N;   // 16384 rows total

// ---------------- scratch (static device memory; no allocation APIs) -----
__device__ __align__(256) float g_dist[(size_t)B * N * N];
__device__ __align__(256) int   g_idx [(size_t)B * N * KNN];
__device__ __align__(256) float g_xcat[(size_t)B * N * 512];
__device__ __align__(256) float g_P   [(size_t)B * N * 256];
__device__ __align__(256) float g_Q   [(size_t)B * N * 256];
__device__ __align__(256) float g_wq  [256 * 128];
__device__ __align__(256) float g_nrm [(size_t)B * N];
__device__ __align__(256) float g_loc [(size_t)B * N * 512];
__device__ __align__(256) float g_emb [(size_t)B * N * 1024];
__device__ __align__(256) float g_glob[(size_t)B * 1024];
__device__ __align__(256) float g_gb  [(size_t)B * 256];
__device__ __align__(256) float g_h1  [(size_t)B * N * 256];
__device__ __align__(256) float g_h2  [(size_t)B * N * 256];

// ======================= helpers =======================
__device__ __forceinline__ uint32_t smem_u32(const void* p) {
    uint32_t a;
    asm("{ .reg .u64 t; cvta.to.shared.u64 t, %1; cvt.u32.u64 %0, t; }"
        : "=r"(a) : "l"(p));
    return a;
}

__device__ __forceinline__ void ldsm4(uint32_t* r, uint32_t addr) {
    asm volatile("ldmatrix.sync.aligned.m8n8.x4.shared.b16 {%0,%1,%2,%3}, [%4];"
                 : "=r"(r[0]), "=r"(r[1]), "=r"(r[2]), "=r"(r[3]) : "r"(addr));
}

__device__ __forceinline__ void mma16816(float* c, const uint32_t* a,
                                         uint32_t b0, uint32_t b1) {
    asm volatile(
        "mma.sync.aligned.m16n8k16.row.col.f32.bf16.bf16.f32 "
        "{%0,%1,%2,%3}, {%4,%5,%6,%7}, {%8,%9}, {%0,%1,%2,%3};"
        : "+f"(c[0]), "+f"(c[1]), "+f"(c[2]), "+f"(c[3])
        : "r"(a[0]), "r"(a[1]), "r"(a[2]), "r"(a[3]), "r"(b0), "r"(b1));
}

// split fp32 -> bf16 hi/lo pairs (packed bf16x2)
__device__ __forceinline__ void split4(float4 v, uint2& h, uint2& l) {
    __nv_bfloat162 ha, hb, la, lb;
    ha.x = __float2bfloat16(v.x); ha.y = __float2bfloat16(v.y);
    hb.x = __float2bfloat16(v.z); hb.y = __float2bfloat16(v.w);
    la.x = __float2bfloat16(v.x - __bfloat162float(ha.x));
    la.y = __float2bfloat16(v.y - __bfloat162float(ha.y));
    lb.x = __float2bfloat16(v.z - __bfloat162float(hb.x));
    lb.y = __float2bfloat16(v.w - __bfloat162float(hb.y));
    h.x = *reinterpret_cast<uint32_t*>(&ha);
    h.y = *reinterpret_cast<uint32_t*>(&hb);
    l.x = *reinterpret_cast<uint32_t*>(&la);
    l.y = *reinterpret_cast<uint32_t*>(&lb);
}

// ============ split-bf16 HMMA GEMM: Out[m,o] = sum_c A[m,c]*W[o,c] ========
// 128x128 tile per CTA, 8 warps (4 in M x 2 in N), warp tile 32x64.
// K multiple of 32 (>=64); M, O multiples of 128.
// Software-pipelined: double-buffered smem planes; global loads for chunk
// ck+2 overlap split+MMA of chunk ck. One barrier per chunk.
// modes: 0 plain | 1 lrelu(acc*s+t) | 3 lrelu((acc+g[(m/nper)*O+o])*s+t)
//        | 4 g[m]+g[o]-2*acc (distance, per-batch g)
constexpr int TSTR = 80;                      // bytes per smem row (64 data + 16 pad)
constexpr int HT_TILE = 128 * TSTR;           // one plane: 10240 B
constexpr int STAGE  = 4 * HT_TILE;           // 40960 B per buffer
constexpr int HT_SMEM = 2 * STAGE;            // 81920 B

__global__ __launch_bounds__(256)
void hgemm_k(const float* __restrict__ A, int lda, long bA,
             const float* __restrict__ W, int ldw, long bW,
             float* __restrict__ Out, int ldo, long bO,
             int K, int mode,
             const float* __restrict__ s, const float* __restrict__ t,
             const float* __restrict__ g, long bG, int nper)
{
    extern __shared__ char smem[];

    const int tid = threadIdx.x, lane = tid & 31, wid = tid >> 5;
    const int m0 = blockIdx.x * 128, n0 = blockIdx.y * 128;
    const int bz = blockIdx.z;
    const float* Ab = A + (long)bz * bA;
    const float* Wb = W + (long)bz * bW;
    const int wm = wid & 3;       // m-block of 32
    const int wn = wid >> 2;      // n-block of 64

    // per-thread staging registers for one chunk (A + W, 4 float4 each)
    float4 avr[4], wvr[4];
    const int srow = tid >> 3;          // 0..31 base row helper (e>>3 for r=0)
    const int sq   = tid & 7;

    auto load_regs = [&](int ck) {
        const int k0 = ck << 5;
#pragma unroll
        for (int r = 0; r < 4; r++) {
            int row = srow + r * 32;
            avr[r] = *(const float4*)(Ab + (long)(m0 + row) * lda + k0 + sq * 4);
            wvr[r] = *(const float4*)(Wb + (long)(n0 + row) * ldw + k0 + sq * 4);
        }
    };
    auto split_sts = [&](int buf) {
        char* pAH = smem + buf * STAGE;
        char* pAL = pAH + HT_TILE;
        char* pWH = pAL + HT_TILE;
        char* pWL = pWH + HT_TILE;
#pragma unroll
        for (int r = 0; r < 4; r++) {
            int so = (srow + r * 32) * TSTR + sq * 8;
            uint2 h, l;
            split4(avr[r], h, l);
            *(uint2*)(pAH + so) = h;
            *(uint2*)(pAL + so) = l;
            split4(wvr[r], h, l);
            *(uint2*)(pWH + so) = h;
            *(uint2*)(pWL + so) = l;
        }
    };

    float acc[2][8][4];
#pragma unroll
    for (int i = 0; i < 2; i++)
#pragma unroll
        for (int j = 0; j < 8; j++)
#pragma unroll
            for (int u = 0; u < 4; u++) acc[i][j][u] = 0.f;

    const uint32_t lrow  = lane & 15;
    const uint32_t lcolb = (lane >> 4) * 16;   // k8-half byte offset
    const uint32_t sb0 = smem_u32(smem);

    const int nch = K >> 5;       // K/32, >= 2
    load_regs(0);
    split_sts(0);
    load_regs(1);
    __syncthreads();

    for (int ck = 0; ck < nch; ck++) {
        if (ck + 1 < nch) split_sts((ck + 1) & 1);
        if (ck + 2 < nch) load_regs(ck + 2);

        const uint32_t sbb = sb0 + (ck & 1) * STAGE;
        const uint32_t sAH = sbb, sAL = sbb + HT_TILE;
        const uint32_t sWH = sbb + 2 * HT_TILE, sWL = sbb + 3 * HT_TILE;

#pragma unroll
        for (int ks = 0; ks < 2; ks++) {
            uint32_t ahi[2][4], alo[2][4];
            uint32_t bhi[4][4], blo[4][4];
            const uint32_t abase = (uint32_t)(wm * 32 + lrow) * TSTR + ks * 32 + lcolb;
#pragma unroll
            for (int mf = 0; mf < 2; mf++) {
                ldsm4(ahi[mf], sAH + abase + mf * 16 * TSTR);
                ldsm4(alo[mf], sAL + abase + mf * 16 * TSTR);
            }
            const uint32_t wbase = (uint32_t)(wn * 64 + lrow) * TSTR + ks * 32 + lcolb;
#pragma unroll
            for (int nt = 0; nt < 4; nt++) {
                ldsm4(bhi[nt], sWH + wbase + nt * 16 * TSTR);
                ldsm4(blo[nt], sWL + wbase + nt * 16 * TSTR);
            }
#pragma unroll
            for (int mf = 0; mf < 2; mf++)
#pragma unroll
                for (int nt = 0; nt < 4; nt++)
#pragma unroll
                    for (int h = 0; h < 2; h++) {
                        float* c = acc[mf][nt * 2 + h];
                        mma16816(c, ahi[mf], bhi[nt][h], bhi[nt][h + 2]);
                        mma16816(c, ahi[mf], blo[nt][h], blo[nt][h + 2]);
                        mma16816(c, alo[mf], bhi[nt][h], bhi[nt][h + 2]);
                    }
        }
        __syncthreads();
    }

    // ---- epilogue (direct stores, as in the 2359us champion) ----
    const int tig = lane & 3, grp = lane >> 2;
    const int O = gridDim.y * 128;
    const float* gB = g + (long)bz * bG;

#pragma unroll
    for (int mf = 0; mf < 2; mf++) {
        const int mA = m0 + wm * 32 + mf * 16 + grp;   // rows mA and mA+8
#pragma unroll
        for (int nf = 0; nf < 8; nf++) {
            const int o = n0 + wn * 64 + nf * 8 + tig * 2;
            float* c = acc[mf][nf];
            float v[4] = {c[0], c[1], c[2], c[3]};
            if (mode == 1) {
                float s0 = s[o], s1 = s[o + 1], t0 = t[o], t1 = t[o + 1];
                v[0] = fmaf(v[0], s0, t0); v[1] = fmaf(v[1], s1, t1);
                v[2] = fmaf(v[2], s0, t0); v[3] = fmaf(v[3], s1, t1);
#pragma unroll
                for (int u = 0; u < 4; u++) v[u] = v[u] >= 0.f ? v[u] : 0.2f * v[u];
            } else if (mode == 3) {
                int g0 = (mA / nper) * O, g1 = ((mA + 8) / nper) * O;
                float s0 = s[o], s1 = s[o + 1], t0 = t[o], t1 = t[o + 1];
                v[0] = fmaf(v[0] + g[g0 + o],     s0, t0);
                v[1] = fmaf(v[1] + g[g0 + o + 1], s1, t1);
                v[2] = fmaf(v[2] + g[g1 + o],     s0, t0);
                v[3] = fmaf(v[3] + g[g1 + o + 1], s1, t1);
#pragma unroll
                for (int u = 0; u < 4; u++) v[u] = v[u] >= 0.f ? v[u] : 0.2f * v[u];
            } else if (mode == 4) {
                float gm0 = gB[mA], gm1 = gB[mA + 8];
                float gn0 = gB[o], gn1 = gB[o + 1];
                v[0] = gm0 + gn0 - 2.f * v[0];
                v[1] = gm0 + gn1 - 2.f * v[1];
                v[2] = gm1 + gn0 - 2.f * v[2];
                v[3] = gm1 + gn1 - 2.f * v[3];
            }
            float* orow0 = Out + (long)bz * bO + (long)mA * ldo + o;
            float* orow1 = orow0 + 8l * ldo;
            *(float2*)orow0 = make_float2(v[0], v[1]);
            *(float2*)orow1 = make_float2(v[2], v[3]);
        }
    }
}

// ======================= fp32 SGEMM (odd shapes) =======================
constexpr int BM = 128, BNt = 128, BK = 8;

__global__ __launch_bounds__(256, 2)
void sgemm_k(const float* __restrict__ A, int lda,
             const float* __restrict__ W, int ldw, int wcol,
             float* __restrict__ Out, int ldo,
             int M, int C, int O, int mode,
             const float* __restrict__ s, const float* __restrict__ t,
             const float* __restrict__ g, int nper)
{
    __shared__ float As[BK][BM + 4];
    __shared__ float Ws[BK][BNt + 4];

    const int tid = threadIdx.x;
    const int tx = tid & 15;
    const int ty = tid >> 4;
    const int m0 = blockIdx.x * BM;
    const int n0 = blockIdx.y * BNt;

    float acc[8][8];
#pragma unroll
    for (int i = 0; i < 8; i++)
#pragma unroll
        for (int j = 0; j < 8; j++) acc[i][j] = 0.f;

    for (int k0 = 0; k0 < C; k0 += BK) {
#pragma unroll
        for (int r = 0; r < 4; r++) {
            int e  = tid + r * 256;
            int mm = e >> 3;
            int kk = e & 7;
            int gk = k0 + kk;
            int gm = m0 + mm;
            As[kk][mm] = (gm < M && gk < C) ? A[(size_t)gm * lda + gk] : 0.f;
            int gn = n0 + mm;
            Ws[kk][mm] = (gn < O && gk < C) ? W[(size_t)gn * ldw + wcol + gk] : 0.f;
        }
        __syncthreads();

#pragma unroll
        for (int kk = 0; kk < BK; kk++) {
            float a[8], bb[8];
#pragma unroll
            for (int i = 0; i < 8; i++) a[i]  = As[kk][ty + 16 * i];
#pragma unroll
            for (int j = 0; j < 8; j++) bb[j] = Ws[kk][tx + 16 * j];
#pragma unroll
            for (int i = 0; i < 8; i++)
#pragma unroll
                for (int j = 0; j < 8; j++)
                    acc[i][j] = fmaf(a[i], bb[j], acc[i][j]);
        }
        __syncthreads();
    }

#pragma unroll
    for (int i = 0; i < 8; i++) {
        int m = m0 + ty + 16 * i;
        if (m >= M) continue;
#pragma unroll
        for (int j = 0; j < 8; j++) {
            int o = n0 + tx + 16 * j;
            if (o >= O) continue;
            float v = acc[i][j];
            if (mode == 1) {
                v = fmaf(v, s[o], t[o]);
                v = v >= 0.f ? v : 0.2f * v;
            } else if (mode == 2) {
                v += s[o];
            } else if (mode == 3) {
                v += g[(m / nper) * O + o];
                v = fmaf(v, s[o], t[o]);
                v = v >= 0.f ? v : 0.2f * v;
            } else if (mode == 4) {
                v = g[m] + g[o] - 2.f * v;
            }
            Out[(size_t)m * ldo + o] = v;
        }
    }
}

// ---------------- squared norms ----------------
__global__ void norms_k(const float* __restrict__ X, int lda, int C,
                        float* __restrict__ out, int M)
{
    int m = blockIdx.x * blockDim.x + threadIdx.x;
    if (m >= M) return;
    const float* p = X + (size_t)m * lda;
    float acc = 0.f;
    for (int c = 0; c < C; c++) acc = fmaf(p[c], p[c], acc);
    out[m] = acc;
}

// ---------------- top-k (k=20 smallest per row) ----------------
__global__ __launch_bounds__(256)
void topk_k(float* __restrict__ D, int* __restrict__ idx)
{
    const int row = blockIdx.x;
    const int b   = row >> 11;
    const int i   = row & (N - 1);
    float* d = D + (size_t)b * N * N + (size_t)i * N;

    __shared__ float sv[N];
    __shared__ float wv[8];
    __shared__ int   wi[8];

    const int tid = threadIdx.x;
    for (int j = tid; j < N; j += 256) sv[j] = d[j];
    __syncthreads();

    for (int kk = 0; kk < KNN; kk++) {
        float bv = 3.3e38f; int bi = N;
        for (int j = tid; j < N; j += 256) {
            float v = sv[j];
            if (v < bv) { bv = v; bi = j; }
        }
#pragma unroll
        for (int o = 16; o > 0; o >>= 1) {
            float v2 = __shfl_down_sync(0xffffffffu, bv, o);
            int   i2 = __shfl_down_sync(0xffffffffu, bi, o);
            if (v2 < bv || (v2 == bv && i2 < bi)) { bv = v2; bi = i2; }
        }
        int w = tid >> 5;
        if ((tid & 31) == 0) { wv[w] = bv; wi[w] = bi; }
        __syncthreads();
        if (tid < 8) {
            bv = wv[tid]; bi = wi[tid];
#pragma unroll
            for (int o = 4; o > 0; o >>= 1) {
                float v2 = __shfl_down_sync(0xffu, bv, o);
                int   i2 = __shfl_down_sync(0xffu, bi, o);
                if (v2 < bv || (v2 == bv && i2 < bi)) { bv = v2; bi = i2; }
            }
            if (tid == 0) {
                idx[(size_t)row * KNN + kk] = bi;
                sv[bi] = 3.35e38f;
            }
        }
        __syncthreads();
    }
}

// ---------------- weight diff: wq = w[:,C:2C] - w[:,0:C] ----------------
__global__ void wdiff_k(const float* __restrict__ w, int C, int O,
                        float* __restrict__ wq)
{
    int e = blockIdx.x * blockDim.x + threadIdx.x;
    if (e >= O * C) return;
    int o = e / C, c = e % C;
    wq[e] = w[(size_t)o * 2 * C + C + c] - w[(size_t)o * 2 * C + c];
}

// ---------------- edgeconv gather + lrelu + max over k ----------------
__global__ void edge_max_k(const float* __restrict__ P,
                           const float* __restrict__ Q,
                           const int* __restrict__ idx,
                           const float* __restrict__ s,
                           const float* __restrict__ t,
                           float* __restrict__ out, int O, int choff)
{
    const int row = blockIdx.x;
    const int b   = row >> 11;
    const int o   = threadIdx.x;

    __shared__ int sj[KNN];
    if (o < KNN) sj[o] = idx[(size_t)row * KNN + o];
    __syncthreads();

    const float q  = Q[(size_t)row * O + o];
    const float ss = s[o], tt = t[o];
    float m = -3.4e38f;
#pragma unroll
    for (int kk = 0; kk < KNN; kk++) {
        int j = sj[kk];
        float p = P[((size_t)(b * N + j)) * O + o];
        float v = fmaf(p + q, ss, tt);
        v = v >= 0.f ? v : 0.2f * v;
        m = fmaxf(m, v);
    }
    out[(size_t)row * 512 + choff + o] = m;
}

// ---------------- global max over N of x_emb ----------------
__global__ void gmax_k(const float* __restrict__ emb, float* __restrict__ glob)
{
    const int b = blockIdx.x;
    const int o = blockIdx.y * 256 + threadIdx.x;
    const float* p = emb + (size_t)b * N * 1024 + o;
    float m = -3.4e38f;
#pragma unroll 8
    for (int n = 0; n < N; n++) m = fmaxf(m, p[(size_t)n << 10]);
    glob[b * 1024 + o] = m;
}

// ---------------- host orchestration ----------------
static inline void run_sgemm(const float* A, int lda, const float* W, int ldw,
                             int wcol, float* Out, int ldo, int M, int C, int O,
                             int mode, const float* s, const float* t,
                             const float* g, int nper)
{
    dim3 grid((M + BM - 1) / BM, (O + BNt - 1) / BNt);
    sgemm_k<<<grid, 256>>>(A, lda, W, ldw, wcol, Out, ldo, M, C, O, mode, s, t, g, nper);
}

static inline void run_tc(const float* A, int lda, long bA,
                          const float* W, int ldw, long bW,
                          float* Out, int ldo, long bO,
                          int M, int K, int O, int nbatch, int mode,
                          const float* s, const float* t,
                          const float* g, long bG, int nper)
{
    dim3 grid(M / 128, O / 128, nbatch);
    hgemm_k<<<grid, 256, HT_SMEM>>>(A, lda, bA, W, ldw, bW, Out, ldo, bO,
                                    K, mode, s, t, g, bG, nper);
}

extern "C" void kernel_launch(void* const* d_in, const int* in_sizes, int n_in,
                              void* d_out, int out_size)
{
    (void)in_sizes; (void)n_in; (void)out_size;
    cudaFuncSetAttribute(hgemm_k, cudaFuncAttributeMaxDynamicSharedMemorySize, HT_SMEM);

    const float* xyz   = (const float*)d_in[0];
    const float* ec1_w = (const float*)d_in[1];
    const float* ec1_s = (const float*)d_in[2];
    const float* ec1_t = (const float*)d_in[3];
    const float* ec2_w = (const float*)d_in[4];
    const float* ec2_s = (const float*)d_in[5];
    const float* ec2_t = (const float*)d_in[6];
    const float* ec3_w = (const float*)d_in[7];
    const float* ec3_s = (const float*)d_in[8];
    const float* ec3_t = (const float*)d_in[9];
    const float* ec4_w = (const float*)d_in[10];
    const float* ec4_s = (const float*)d_in[11];
    const float* ec4_t = (const float*)d_in[12];
    const float* fuse_w = (const float*)d_in[13];
    const float* fuse_s = (const float*)d_in[14];
    const float* fuse_t = (const float*)d_in[15];
    const float* emb_w = (const float*)d_in[16];
    const float* emb_s = (const float*)d_in[17];
    const float* emb_t = (const float*)d_in[18];
    const float* h1_w  = (const float*)d_in[19];
    const float* h1_s  = (const float*)d_in[20];
    const float* h1_t  = (const float*)d_in[21];
    const float* h2_w  = (const float*)d_in[22];
    const float* h2_s  = (const float*)d_in[23];
    const float* h2_t  = (const float*)d_in[24];
    const float* h3_w  = (const float*)d_in[25];
    const float* h3_b  = (const float*)d_in[26];
    float* out = (float*)d_out;

    float *dist, *xcat, *P, *Q, *wq, *nrm, *loc, *emb, *glob, *gb, *h1, *h2;
    int* idx;
    cudaGetSymbolAddress((void**)&dist, g_dist);
    cudaGetSymbolAddress((void**)&idx,  g_idx);
    cudaGetSymbolAddress((void**)&xcat, g_xcat);
    cudaGetSymbolAddress((void**)&P,    g_P);
    cudaGetSymbolAddress((void**)&Q,    g_Q);
    cudaGetSymbolAddress((void**)&wq,   g_wq);
    cudaGetSymbolAddress((void**)&nrm,  g_nrm);
    cudaGetSymbolAddress((void**)&loc,  g_loc);
    cudaGetSymbolAddress((void**)&emb,  g_emb);
    cudaGetSymbolAddress((void**)&glob, g_glob);
    cudaGetSymbolAddress((void**)&gb,   g_gb);
    cudaGetSymbolAddress((void**)&h1,   g_h1);
    cudaGetSymbolAddress((void**)&h2,   g_h2);

    // ---------- layer 1 (C=3: fp32 path everywhere) ----------
    norms_k<<<(BN_ + 255) / 256, 256>>>(xyz, 3, 3, nrm, BN_);
    for (int b = 0; b < B; b++) {
        const float* Xb = xyz + (size_t)b * N * 3;
        run_sgemm(Xb, 3, Xb, 3, 0, dist + (size_t)b * N * N, N,
                  N, 3, N, 4, nullptr, nullptr, nrm + b * N, 0);
    }
    topk_k<<<BN_, 256>>>(dist, idx);
    wdiff_k<<<(64 * 3 + 255) / 256, 256>>>(ec1_w, 3, 64, wq);
    run_sgemm(xyz, 3, ec1_w, 6, 0, P, 64, BN_, 3, 64, 0, nullptr, nullptr, nullptr, 0);
    run_sgemm(xyz, 3, wq,    3, 0, Q, 64, BN_, 3, 64, 0, nullptr, nullptr, nullptr, 0);
    edge_max_k<<<BN_, 64>>>(P, Q, idx, ec1_s, ec1_t, xcat, 64, 0);

    // ---------- layer 2 (C=64, O=64: HMMA dist, fp32 P/Q) ----------
    {
        const float* X = xcat;  // lda 512
        norms_k<<<(BN_ + 255) / 256, 256>>>(X, 512, 64, nrm, BN_);
        run_tc(X, 512, (long)N * 512, X, 512, (long)N * 512,
               dist, N, (long)N * N, N, 64, N, B, 4,
               nullptr, nullptr, nrm, N, 0);
        topk_k<<<BN_, 256>>>(dist, idx);
        wdiff_k<<<(64 * 64 + 255) / 256, 256>>>(ec2_w, 64, 64, wq);
        run_sgemm(X, 512, ec2_w, 128, 0, P, 64, BN_, 64, 64, 0, nullptr, nullptr, nullptr, 0);
        run_sgemm(X, 512, wq,    64,  0, Q, 64, BN_, 64, 64, 0, nullptr, nullptr, nullptr, 0);
        edge_max_k<<<BN_, 64>>>(P, Q, idx, ec2_s, ec2_t, xcat, 64, 64);
    }

    // ---------- layer 3 (C=64, O=128: HMMA) ----------
    {
        const float* X = xcat + 64;
        norms_k<<<(BN_ + 255) / 256, 256>>>(X, 512, 64, nrm, BN_);
        run_tc(X, 512, (long)N * 512, X, 512, (long)N * 512,
               dist, N, (long)N * N, N, 64, N, B, 4,
               nullptr, nullptr, nrm, N, 0);
        topk_k<<<BN_, 256>>>(dist, idx);
        wdiff_k<<<(128 * 64 + 255) / 256, 256>>>(ec3_w, 64, 128, wq);
        run_tc(X, 512, 0, ec3_w, 128, 0, P, 128, 0, BN_, 64, 128, 1, 0,
               nullptr, nullptr, nullptr, 0, 0);
        run_tc(X, 512, 0, wq, 64, 0, Q, 128, 0, BN_, 64, 128, 1, 0,
               nullptr, nullptr, nullptr, 0, 0);
        edge_max_k<<<BN_, 128>>>(P, Q, idx, ec3_s, ec3_t, xcat, 128, 128);
    }

    // ---------- layer 4 (C=128, O=256: HMMA) ----------
    {
        const float* X = xcat + 128;
        norms_k<<<(BN_ + 255) / 256, 256>>>(X, 512, 128, nrm, BN_);
        run_tc(X, 512, (long)N * 512, X, 512, (long)N * 512,
               dist, N, (long)N * N, N, 128, N, B, 4,
               nullptr, nullptr, nrm, N, 0);
        topk_k<<<BN_, 256>>>(dist, idx);
        wdiff_k<<<(256 * 128 + 255) / 256, 256>>>(ec4_w, 128, 256, wq);
        run_tc(X, 512, 0, ec4_w, 256, 0, P, 256, 0, BN_, 128, 256, 1, 0,
               nullptr, nullptr, nullptr, 0, 0);
        run_tc(X, 512, 0, wq, 128, 0, Q, 256, 0, BN_, 128, 256, 1, 0,
               nullptr, nullptr, nullptr, 0, 0);
        edge_max_k<<<BN_, 256>>>(P, Q, idx, ec4_s, ec4_t, xcat, 256, 256);
    }

    // fuse: 512 -> 512 (HMMA)
    run_tc(xcat, 512, 0, fuse_w, 512, 0, loc, 512, 0, BN_, 512, 512, 1, 1,
           fuse_s, fuse_t, nullptr, 0, 0);
    // emb: 512 -> 1024 (HMMA), then global max over N
    run_tc(loc, 512, 0, emb_w, 512, 0, emb, 1024, 0, BN_, 512, 1024, 1, 1,
           emb_s, emb_t, nullptr, 0, 0);
    gmax_k<<<dim3(B, 4), 256>>>(emb, glob);
    // gb[b,o] = glob[b] @ h1_w[o, 512:1536]  (tiny: fp32)
    run_sgemm(glob, 1024, h1_w, 1536, 512, gb, 256, B, 1024, 256, 0,
              nullptr, nullptr, nullptr, 0);
    // h1 = lrelu((loc @ h1_w[:, :512]^T + gb[b]) * s + t)  (HMMA, mode 3)
    run_tc(loc, 512, 0, h1_w, 1536, 0, h1, 256, 0, BN_, 512, 256, 1, 3,
           h1_s, h1_t, gb, 0, N);
    // h2 (HMMA)
    run_tc(h1, 256, 0, h2_w, 256, 0, h2, 256, 0, BN_, 256, 256, 1, 1,
           h2_s, h2_t, nullptr, 0, 0);
    // logits = h2 @ h3_w^T + b (O=13: fp32)
    run_sgemm(h2, 256, h3_w, 256, 0, out, 13, BN_, 256, 13, 2,
              h3_b, nullptr, nullptr, 0);
}

// round 14
// speedup vs baseline: 1.1560x; 1.0558x over previous
#include <cuda_runtime.h>
#include <cuda_bf16.h>
#include <cstdint>
#include <cstddef>

// ---------------- problem constants ----------------
constexpr int B = 8;
constexpr int N = 2048;
constexpr int KNN = 20;
constexpr int BN_ = B * N;   // 16384 rows total

// ---------------- scratch (static device memory; no allocation APIs) -----
__device__ __align__(256) int   g_idx [(size_t)B * N * KNN];
__device__ __align__(256) float g_xcat[(size_t)B * N * 512];
__device__ __align__(256) float g_P   [(size_t)B * N * 256];
__device__ __align__(256) float g_Q   [(size_t)B * N * 256];
__device__ __align__(256) float g_wq  [256 * 128];
__device__ __align__(256) float g_nrm [(size_t)B * N];
__device__ __align__(256) float g_loc [(size_t)B * N * 512];
__device__ __align__(256) float g_emb [(size_t)B * N * 1024];
__device__ __align__(256) float g_glob[(size_t)B * 1024];
__device__ __align__(256) float g_gb  [(size_t)B * 256];
__device__ __align__(256) float g_h1  [(size_t)B * N * 256];
__device__ __align__(256) float g_h2  [(size_t)B * N * 256];

// ======================= helpers =======================
__device__ __forceinline__ uint32_t smem_u32(const void* p) {
    uint32_t a;
    asm("{ .reg .u64 t; cvta.to.shared.u64 t, %1; cvt.u32.u64 %0, t; }"
        : "=r"(a) : "l"(p));
    return a;
}

__device__ __forceinline__ void ldsm4(uint32_t* r, uint32_t addr) {
    asm volatile("ldmatrix.sync.aligned.m8n8.x4.shared.b16 {%0,%1,%2,%3}, [%4];"
                 : "=r"(r[0]), "=r"(r[1]), "=r"(r[2]), "=r"(r[3]) : "r"(addr));
}

__device__ __forceinline__ void mma16816(float* c, const uint32_t* a,
                                         uint32_t b0, uint32_t b1) {
    asm volatile(
        "mma.sync.aligned.m16n8k16.row.col.f32.bf16.bf16.f32 "
        "{%0,%1,%2,%3}, {%4,%5,%6,%7}, {%8,%9}, {%0,%1,%2,%3};"
        : "+f"(c[0]), "+f"(c[1]), "+f"(c[2]), "+f"(c[3])
        : "r"(a[0]), "r"(a[1]), "r"(a[2]), "r"(a[3]), "r"(b0), "r"(b1));
}

// split fp32 -> bf16 hi/lo pairs (packed bf16x2)
__device__ __forceinline__ void split4(float4 v, uint2& h, uint2& l) {
    __nv_bfloat162 ha, hb, la, lb;
    ha.x = __float2bfloat16(v.x); ha.y = __float2bfloat16(v.y);
    hb.x = __float2bfloat16(v.z); hb.y = __float2bfloat16(v.w);
    la.x = __float2bfloat16(v.x - __bfloat162float(ha.x));
    la.y = __float2bfloat16(v.y - __bfloat162float(ha.y));
    lb.x = __float2bfloat16(v.z - __bfloat162float(hb.x));
    lb.y = __float2bfloat16(v.w - __bfloat162float(hb.y));
    h.x = *reinterpret_cast<uint32_t*>(&ha);
    h.y = *reinterpret_cast<uint32_t*>(&hb);
    l.x = *reinterpret_cast<uint32_t*>(&la);
    l.y = *reinterpret_cast<uint32_t*>(&lb);
}

constexpr int TSTR = 80;                      // bytes per smem row (64 data + 16 pad)
constexpr int HT_TILE = 128 * TSTR;           // one plane: 10240 B
constexpr int HT_SMEM = 4 * HT_TILE;          // 40960 B

// ============ split-bf16 HMMA GEMM: Out[m,o] = sum_c A[m,c]*W[o,c] ========
// (unchanged from the 2359us champion)
__global__ __launch_bounds__(256)
void hgemm_k(const float* __restrict__ A, int lda, long bA,
             const float* __restrict__ W, int ldw, long bW,
             float* __restrict__ Out, int ldo, long bO,
             int K, int mode,
             const float* __restrict__ s, const float* __restrict__ t,
             const float* __restrict__ g, long bG, int nper)
{
    extern __shared__ char smem[];
    char* pAH = smem;
    char* pAL = smem + HT_TILE;
    char* pWH = smem + 2 * HT_TILE;
    char* pWL = smem + 3 * HT_TILE;
    const uint32_t sAH = smem_u32(pAH), sAL = smem_u32(pAL);
    const uint32_t sWH = smem_u32(pWH), sWL = smem_u32(pWL);

    const int tid = threadIdx.x, lane = tid & 31, wid = tid >> 5;
    const int m0 = blockIdx.x * 128, n0 = blockIdx.y * 128;
    const int bz = blockIdx.z;
    const float* Ab = A + (long)bz * bA;
    const float* Wb = W + (long)bz * bW;
    const int wm = wid & 3;
    const int wn = wid >> 2;

    float acc[2][8][4];
#pragma unroll
    for (int i = 0; i < 2; i++)
#pragma unroll
        for (int j = 0; j < 8; j++)
#pragma unroll
            for (int u = 0; u < 4; u++) acc[i][j][u] = 0.f;

    const uint32_t lrow  = lane & 15;
    const uint32_t lcolb = (lane >> 4) * 16;

    for (int k0 = 0; k0 < K; k0 += 32) {
#pragma unroll
        for (int r = 0; r < 4; r++) {
            int e   = tid + r * 256;
            int row = e >> 3;
            int q   = e & 7;
            int so  = row * TSTR + q * 8;
            float4 av = *(const float4*)(Ab + (long)(m0 + row) * lda + k0 + q * 4);
            float4 wv = *(const float4*)(Wb + (long)(n0 + row) * ldw + k0 + q * 4);
            uint2 h, l;
            split4(av, h, l);
            *(uint2*)(pAH + so) = h;
            *(uint2*)(pAL + so) = l;
            split4(wv, h, l);
            *(uint2*)(pWH + so) = h;
            *(uint2*)(pWL + so) = l;
        }
        __syncthreads();

#pragma unroll
        for (int ks = 0; ks < 2; ks++) {
            uint32_t ahi[2][4], alo[2][4];
            uint32_t bhi[4][4], blo[4][4];
            const uint32_t abase = (uint32_t)(wm * 32 + lrow) * TSTR + ks * 32 + lcolb;
#pragma unroll
            for (int mf = 0; mf < 2; mf++) {
                ldsm4(ahi[mf], sAH + abase + mf * 16 * TSTR);
                ldsm4(alo[mf], sAL + abase + mf * 16 * TSTR);
            }
            const uint32_t wbase = (uint32_t)(wn * 64 + lrow) * TSTR + ks * 32 + lcolb;
#pragma unroll
            for (int nt = 0; nt < 4; nt++) {
                ldsm4(bhi[nt], sWH + wbase + nt * 16 * TSTR);
                ldsm4(blo[nt], sWL + wbase + nt * 16 * TSTR);
            }
#pragma unroll
            for (int mf = 0; mf < 2; mf++)
#pragma unroll
                for (int nt = 0; nt < 4; nt++)
#pragma unroll
                    for (int h = 0; h < 2; h++) {
                        float* c = acc[mf][nt * 2 + h];
                        mma16816(c, ahi[mf], bhi[nt][h], bhi[nt][h + 2]);
                        mma16816(c, ahi[mf], blo[nt][h], blo[nt][h + 2]);
                        mma16816(c, alo[mf], bhi[nt][h], bhi[nt][h + 2]);
                    }
        }
        __syncthreads();
    }

    const int tig = lane & 3, grp = lane >> 2;
    const int O = gridDim.y * 128;
    const float* gB = g + (long)bz * bG;

#pragma unroll
    for (int mf = 0; mf < 2; mf++) {
        const int mA = m0 + wm * 32 + mf * 16 + grp;
#pragma unroll
        for (int nf = 0; nf < 8; nf++) {
            const int o = n0 + wn * 64 + nf * 8 + tig * 2;
            float* c = acc[mf][nf];
            float v[4] = {c[0], c[1], c[2], c[3]};
            if (mode == 1) {
                float s0 = s[o], s1 = s[o + 1], t0 = t[o], t1 = t[o + 1];
                v[0] = fmaf(v[0], s0, t0); v[1] = fmaf(v[1], s1, t1);
                v[2] = fmaf(v[2], s0, t0); v[3] = fmaf(v[3], s1, t1);
#pragma unroll
                for (int u = 0; u < 4; u++) v[u] = v[u] >= 0.f ? v[u] : 0.2f * v[u];
            } else if (mode == 3) {
                int g0 = (mA / nper) * O, g1 = ((mA + 8) / nper) * O;
                float s0 = s[o], s1 = s[o + 1], t0 = t[o], t1 = t[o + 1];
                v[0] = fmaf(v[0] + g[g0 + o],     s0, t0);
                v[1] = fmaf(v[1] + g[g0 + o + 1], s1, t1);
                v[2] = fmaf(v[2] + g[g1 + o],     s0, t0);
                v[3] = fmaf(v[3] + g[g1 + o + 1], s1, t1);
#pragma unroll
                for (int u = 0; u < 4; u++) v[u] = v[u] >= 0.f ? v[u] : 0.2f * v[u];
            } else if (mode == 4) {
                float gm0 = gB[mA], gm1 = gB[mA + 8];
                float gn0 = gB[o], gn1 = gB[o + 1];
                v[0] = gm0 + gn0 - 2.f * v[0];
                v[1] = gm0 + gn1 - 2.f * v[1];
                v[2] = gm1 + gn0 - 2.f * v[2];
                v[3] = gm1 + gn1 - 2.f * v[3];
            }
            float* orow0 = Out + (long)bz * bO + (long)mA * ldo + o;
            float* orow1 = orow0 + 8l * ldo;
            *(float2*)orow0 = make_float2(v[0], v[1]);
            *(float2*)orow1 = make_float2(v[2], v[3]);
        }
    }
}

// ============ fused dist + top-20 (HMMA layers, K=64/128) =================
// Grid (16, 1, 8): CTA = (row-block of 128, batch). Per column-tile of 128:
// HMMA Gram tile -> d = n_i + n_j - 2*dot in padded smem -> per-row streaming
// top-20 selection (threshold in register, list in smem). No dist matrix in
// global memory, no separate topk kernel.
constexpr int DSTR = 129;                       // D row stride (floats), conflict-free
constexpr int HD_SMEM = HT_SMEM + 128 * DSTR * 4 + 128 * KNN * 4 + 128 * KNN * 4;

__global__ __launch_bounds__(256)
void hdist_topk_k(const float* __restrict__ X, int lda, long bX,
                  const float* __restrict__ nrm, int K,
                  int* __restrict__ idx)
{
    extern __shared__ char smem[];
    char* pAH = smem;
    char* pAL = smem + HT_TILE;
    char* pWH = smem + 2 * HT_TILE;
    char* pWL = smem + 3 * HT_TILE;
    const uint32_t sAH = smem_u32(pAH), sAL = smem_u32(pAL);
    const uint32_t sWH = smem_u32(pWH), sWL = smem_u32(pWL);
    float* D    = (float*)(smem + HT_SMEM);
    float* tval = D + 128 * DSTR;
    int*   tidx = (int*)(tval + 128 * KNN);

    const int tid = threadIdx.x, lane = tid & 31, wid = tid >> 5;
    const int m0 = blockIdx.x * 128;
    const int bz = blockIdx.z;
    const float* Xb = X + (long)bz * bX;
    const float* nb = nrm + (long)bz * N;
    const int wm = wid & 3;
    const int wn = wid >> 2;
    const uint32_t lrow  = lane & 15;
    const uint32_t lcolb = (lane >> 4) * 16;
    const int tig = lane & 3, grp = lane >> 2;

    if (tid < 128) {
#pragma unroll
        for (int k = 0; k < KNN; k++) tval[tid * KNN + k] = 3.4e38f;
    }
    float tau = 3.4e38f;
    __syncthreads();

    for (int ct = 0; ct < 16; ct++) {
        const int n0 = ct * 128;
        float acc[2][8][4];
#pragma unroll
        for (int i = 0; i < 2; i++)
#pragma unroll
            for (int j = 0; j < 8; j++)
#pragma unroll
                for (int u = 0; u < 4; u++) acc[i][j][u] = 0.f;

        for (int k0 = 0; k0 < K; k0 += 32) {
#pragma unroll
            for (int r = 0; r < 4; r++) {
                int e   = tid + r * 256;
                int row = e >> 3;
                int q   = e & 7;
                int so  = row * TSTR + q * 8;
                float4 av = *(const float4*)(Xb + (long)(m0 + row) * lda + k0 + q * 4);
                float4 wv = *(const float4*)(Xb + (long)(n0 + row) * lda + k0 + q * 4);
                uint2 h, l;
                split4(av, h, l);
                *(uint2*)(pAH + so) = h;
                *(uint2*)(pAL + so) = l;
                split4(wv, h, l);
                *(uint2*)(pWH + so) = h;
                *(uint2*)(pWL + so) = l;
            }
            __syncthreads();

#pragma unroll
            for (int ks = 0; ks < 2; ks++) {
                uint32_t ahi[2][4], alo[2][4];
                uint32_t bhi[4][4], blo[4][4];
                const uint32_t abase = (uint32_t)(wm * 32 + lrow) * TSTR + ks * 32 + lcolb;
#pragma unroll
                for (int mf = 0; mf < 2; mf++) {
                    ldsm4(ahi[mf], sAH + abase + mf * 16 * TSTR);
                    ldsm4(alo[mf], sAL + abase + mf * 16 * TSTR);
                }
                const uint32_t wbase = (uint32_t)(wn * 64 + lrow) * TSTR + ks * 32 + lcolb;
#pragma unroll
                for (int nt = 0; nt < 4; nt++) {
                    ldsm4(bhi[nt], sWH + wbase + nt * 16 * TSTR);
                    ldsm4(blo[nt], sWL + wbase + nt * 16 * TSTR);
                }
#pragma unroll
                for (int mf = 0; mf < 2; mf++)
#pragma unroll
                    for (int nt = 0; nt < 4; nt++)
#pragma unroll
                        for (int h = 0; h < 2; h++) {
                            float* c = acc[mf][nt * 2 + h];
                            mma16816(c, ahi[mf], bhi[nt][h], bhi[nt][h + 2]);
                            mma16816(c, ahi[mf], blo[nt][h], blo[nt][h + 2]);
                            mma16816(c, alo[mf], bhi[nt][h], bhi[nt][h + 2]);
                        }
            }
            __syncthreads();
        }

        // distance tile into padded smem
#pragma unroll
        for (int mf = 0; mf < 2; mf++) {
            const int rl = wm * 32 + mf * 16 + grp;
            const float gm0 = nb[m0 + rl], gm1 = nb[m0 + rl + 8];
#pragma unroll
            for (int nf = 0; nf < 8; nf++) {
                const int c = wn * 64 + nf * 8 + tig * 2;
                const float gn0 = nb[n0 + c], gn1 = nb[n0 + c + 1];
                float* a = acc[mf][nf];
                D[rl * DSTR + c]           = gm0 + gn0 - 2.f * a[0];
                D[rl * DSTR + c + 1]       = gm0 + gn1 - 2.f * a[1];
                D[(rl + 8) * DSTR + c]     = gm1 + gn0 - 2.f * a[2];
                D[(rl + 8) * DSTR + c + 1] = gm1 + gn1 - 2.f * a[3];
            }
        }
        __syncthreads();

        // per-row streaming top-20
        if (tid < 128) {
            const float* dr = D + tid * DSTR;
            float* tv = tval + tid * KNN;
            int*   ti = tidx + tid * KNN;
            for (int j = 0; j < 128; j++) {
                float v = dr[j];
                if (v < tau) {
                    int mk = 0; float mx = tv[0];
#pragma unroll
                    for (int k = 1; k < KNN; k++)
                        if (tv[k] > mx) { mx = tv[k]; mk = k; }
                    tv[mk] = v; ti[mk] = n0 + j;
                    mx = tv[0];
#pragma unroll
                    for (int k = 1; k < KNN; k++) mx = fmaxf(mx, tv[k]);
                    tau = mx;
                }
            }
        }
        __syncthreads();
    }

    if (tid < 128) {
        int* op = idx + ((long)bz * N + m0 + tid) * KNN;
        int* ti = tidx + tid * KNN;
#pragma unroll
        for (int k = 0; k < KNN; k++) op[k] = ti[k];
    }
}

// ============ fused dist + top-20 for layer 1 (C=3, fp32) =================
__global__ __launch_bounds__(256)
void dist3_topk_k(const float* __restrict__ xyz,
                  const float* __restrict__ nrm,
                  int* __restrict__ idx)
{
    __shared__ float Ax[128][3];
    __shared__ float Wx[128][4];
    __shared__ float Wn[128];
    __shared__ float tval[128 * KNN];
    __shared__ int   tidx[128 * KNN];

    const int tid = threadIdx.x;
    const int m0 = blockIdx.x * 128;
    const int bz = blockIdx.z;
    const float* Xb = xyz + (long)bz * N * 3;
    const float* nb = nrm + (long)bz * N;

    for (int e = tid; e < 384; e += 256) Ax[e / 3][e % 3] = Xb[m0 * 3 + e];
    if (tid < 128) {
#pragma unroll
        for (int k = 0; k < KNN; k++) tval[tid * KNN + k] = 3.4e38f;
    }
    __syncthreads();

    float ar0 = 0.f, ar1 = 0.f, ar2 = 0.f, na = 0.f;
    if (tid < 128) {
        ar0 = Ax[tid][0]; ar1 = Ax[tid][1]; ar2 = Ax[tid][2];
        na = nb[m0 + tid];
    }
    float tau = 3.4e38f;

    for (int ct = 0; ct < 16; ct++) {
        const int n0 = ct * 128;
        __syncthreads();
        for (int e = tid; e < 384; e += 256) Wx[e / 3][e % 3] = Xb[n0 * 3 + e];
        if (tid < 128) Wn[tid] = nb[n0 + tid];
        __syncthreads();

        if (tid < 128) {
            float* tv = tval + tid * KNN;
            int*   ti = tidx + tid * KNN;
            for (int j = 0; j < 128; j++) {
                float dot = ar0 * Wx[j][0] + ar1 * Wx[j][1] + ar2 * Wx[j][2];
                float v = na + Wn[j] - 2.f * dot;
                if (v < tau) {
                    int mk = 0; float mx = tv[0];
#pragma unroll
                    for (int k = 1; k < KNN; k++)
                        if (tv[k] > mx) { mx = tv[k]; mk = k; }
                    tv[mk] = v; ti[mk] = n0 + j;
                    mx = tv[0];
#pragma unroll
                    for (int k = 1; k < KNN; k++) mx = fmaxf(mx, tv[k]);
                    tau = mx;
                }
            }
        }
    }
    __syncthreads();
    if (tid < 128) {
        int* op = idx + ((long)bz * N + m0 + tid) * KNN;
        int* ti = tidx + tid * KNN;
#pragma unroll
        for (int k = 0; k < KNN; k++) op[k] = ti[k];
    }
}

// ======================= fp32 SGEMM (odd shapes) =======================
constexpr int BM = 128, BNt = 128, BK = 8;

__global__ __launch_bounds__(256, 2)
void sgemm_k(const float* __restrict__ A, int lda,
             const float* __restrict__ W, int ldw, int wcol,
             float* __restrict__ Out, int ldo,
             int M, int C, int O, int mode,
             const float* __restrict__ s, const float* __restrict__ t,
             const float* __restrict__ g, int nper)
{
    __shared__ float As[BK][BM + 4];
    __shared__ float Ws[BK][BNt + 4];

    const int tid = threadIdx.x;
    const int tx = tid & 15;
    const int ty = tid >> 4;
    const int m0 = blockIdx.x * BM;
    const int n0 = blockIdx.y * BNt;

    float acc[8][8];
#pragma unroll
    for (int i = 0; i < 8; i++)
#pragma unroll
        for (int j = 0; j < 8; j++) acc[i][j] = 0.f;

    for (int k0 = 0; k0 < C; k0 += BK) {
#pragma unroll
        for (int r = 0; r < 4; r++) {
            int e  = tid + r * 256;
            int mm = e >> 3;
            int kk = e & 7;
            int gk = k0 + kk;
            int gm = m0 + mm;
            As[kk][mm] = (gm < M && gk < C) ? A[(size_t)gm * lda + gk] : 0.f;
            int gn = n0 + mm;
            Ws[kk][mm] = (gn < O && gk < C) ? W[(size_t)gn * ldw + wcol + gk] : 0.f;
        }
        __syncthreads();

#pragma unroll
        for (int kk = 0; kk < BK; kk++) {
            float a[8], bb[8];
#pragma unroll
            for (int i = 0; i < 8; i++) a[i]  = As[kk][ty + 16 * i];
#pragma unroll
            for (int j = 0; j < 8; j++) bb[j] = Ws[kk][tx + 16 * j];
#pragma unroll
            for (int i = 0; i < 8; i++)
#pragma unroll
                for (int j = 0; j < 8; j++)
                    acc[i][j] = fmaf(a[i], bb[j], acc[i][j]);
        }
        __syncthreads();
    }

#pragma unroll
    for (int i = 0; i < 8; i++) {
        int m = m0 + ty + 16 * i;
        if (m >= M) continue;
#pragma unroll
        for (int j = 0; j < 8; j++) {
            int o = n0 + tx + 16 * j;
            if (o >= O) continue;
            float v = acc[i][j];
            if (mode == 1) {
                v = fmaf(v, s[o], t[o]);
                v = v >= 0.f ? v : 0.2f * v;
            } else if (mode == 2) {
                v += s[o];
            } else if (mode == 3) {
                v += g[(m / nper) * O + o];
                v = fmaf(v, s[o], t[o]);
                v = v >= 0.f ? v : 0.2f * v;
            }
            Out[(size_t)m * ldo + o] = v;
        }
    }
}

// ---------------- squared norms ----------------
__global__ void norms_k(const float* __restrict__ X, int lda, int C,
                        float* __restrict__ out, int M)
{
    int m = blockIdx.x * blockDim.x + threadIdx.x;
    if (m >= M) return;
    const float* p = X + (size_t)m * lda;
    float acc = 0.f;
    for (int c = 0; c < C; c++) acc = fmaf(p[c], p[c], acc);
    out[m] = acc;
}

// ---------------- weight diff: wq = w[:,C:2C] - w[:,0:C] ----------------
__global__ void wdiff_k(const float* __restrict__ w, int C, int O,
                        float* __restrict__ wq)
{
    int e = blockIdx.x * blockDim.x + threadIdx.x;
    if (e >= O * C) return;
    int o = e / C, c = e % C;
    wq[e] = w[(size_t)o * 2 * C + C + c] - w[(size_t)o * 2 * C + c];
}

// ---------------- edgeconv gather + lrelu + max over k ----------------
__global__ void edge_max_k(const float* __restrict__ P,
                           const float* __restrict__ Q,
                           const int* __restrict__ idx,
                           const float* __restrict__ s,
                           const float* __restrict__ t,
                           float* __restrict__ out, int O, int choff)
{
    const int row = blockIdx.x;
    const int b   = row >> 11;
    const int o   = threadIdx.x;

    __shared__ int sj[KNN];
    if (o < KNN) sj[o] = idx[(size_t)row * KNN + o];
    __syncthreads();

    const float q  = Q[(size_t)row * O + o];
    const float ss = s[o], tt = t[o];
    float m = -3.4e38f;
#pragma unroll
    for (int kk = 0; kk < KNN; kk++) {
        int j = sj[kk];
        float p = P[((size_t)(b * N + j)) * O + o];
        float v = fmaf(p + q, ss, tt);
        v = v >= 0.f ? v : 0.2f * v;
        m = fmaxf(m, v);
    }
    out[(size_t)row * 512 + choff + o] = m;
}

// ---------------- global max over N of x_emb ----------------
__global__ void gmax_k(const float* __restrict__ emb, float* __restrict__ glob)
{
    const int b = blockIdx.x;
    const int o = blockIdx.y * 256 + threadIdx.x;
    const float* p = emb + (size_t)b * N * 1024 + o;
    float m = -3.4e38f;
#pragma unroll 8
    for (int n = 0; n < N; n++) m = fmaxf(m, p[(size_t)n << 10]);
    glob[b * 1024 + o] = m;
}

// ---------------- host orchestration ----------------
static inline void run_sgemm(const float* A, int lda, const float* W, int ldw,
                             int wcol, float* Out, int ldo, int M, int C, int O,
                             int mode, const float* s, const float* t,
                             const float* g, int nper)
{
    dim3 grid((M + BM - 1) / BM, (O + BNt - 1) / BNt);
    sgemm_k<<<grid, 256>>>(A, lda, W, ldw, wcol, Out, ldo, M, C, O, mode, s, t, g, nper);
}

static inline void run_tc(const float* A, int lda, long bA,
                          const float* W, int ldw, long bW,
                          float* Out, int ldo, long bO,
                          int M, int K, int O, int nbatch, int mode,
                          const float* s, const float* t,
                          const float* g, long bG, int nper)
{
    dim3 grid(M / 128, O / 128, nbatch);
    hgemm_k<<<grid, 256, HT_SMEM>>>(A, lda, bA, W, ldw, bW, Out, ldo, bO,
                                    K, mode, s, t, g, bG, nper);
}

extern "C" void kernel_launch(void* const* d_in, const int* in_sizes, int n_in,
                              void* d_out, int out_size)
{
    (void)in_sizes; (void)n_in; (void)out_size;
    cudaFuncSetAttribute(hgemm_k, cudaFuncAttributeMaxDynamicSharedMemorySize, HT_SMEM);
    cudaFuncSetAttribute(hdist_topk_k, cudaFuncAttributeMaxDynamicSharedMemorySize, HD_SMEM);

    const float* xyz   = (const float*)d_in[0];
    const float* ec1_w = (const float*)d_in[1];
    const float* ec1_s = (const float*)d_in[2];
    const float* ec1_t = (const float*)d_in[3];
    const float* ec2_w = (const float*)d_in[4];
    const float* ec2_s = (const float*)d_in[5];
    const float* ec2_t = (const float*)d_in[6];
    const float* ec3_w = (const float*)d_in[7];
    const float* ec3_s = (const float*)d_in[8];
    const float* ec3_t = (const float*)d_in[9];
    const float* ec4_w = (const float*)d_in[10];
    const float* ec4_s = (const float*)d_in[11];
    const float* ec4_t = (const float*)d_in[12];
    const float* fuse_w = (const float*)d_in[13];
    const float* fuse_s = (const float*)d_in[14];
    const float* fuse_t = (const float*)d_in[15];
    const float* emb_w = (const float*)d_in[16];
    const float* emb_s = (const float*)d_in[17];
    const float* emb_t = (const float*)d_in[18];
    const float* h1_w  = (const float*)d_in[19];
    const float* h1_s  = (const float*)d_in[20];
    const float* h1_t  = (const float*)d_in[21];
    const float* h2_w  = (const float*)d_in[22];
    const float* h2_s  = (const float*)d_in[23];
    const float* h2_t  = (const float*)d_in[24];
    const float* h3_w  = (const float*)d_in[25];
    const float* h3_b  = (const float*)d_in[26];
    float* out = (float*)d_out;

    float *xcat, *P, *Q, *wq, *nrm, *loc, *emb, *glob, *gb, *h1, *h2;
    int* idx;
    cudaGetSymbolAddress((void**)&idx,  g_idx);
    cudaGetSymbolAddress((void**)&xcat, g_xcat);
    cudaGetSymbolAddress((void**)&P,    g_P);
    cudaGetSymbolAddress((void**)&Q,    g_Q);
    cudaGetSymbolAddress((void**)&wq,   g_wq);
    cudaGetSymbolAddress((void**)&nrm,  g_nrm);
    cudaGetSymbolAddress((void**)&loc,  g_loc);
    cudaGetSymbolAddress((void**)&emb,  g_emb);
    cudaGetSymbolAddress((void**)&glob, g_glob);
    cudaGetSymbolAddress((void**)&gb,   g_gb);
    cudaGetSymbolAddress((void**)&h1,   g_h1);
    cudaGetSymbolAddress((void**)&h2,   g_h2);

    const dim3 dgrid(16, 1, 8);

    // ---------- layer 1 (C=3: fused fp32 dist+topk) ----------
    norms_k<<<(BN_ + 255) / 256, 256>>>(xyz, 3, 3, nrm, BN_);
    dist3_topk_k<<<dgrid, 256>>>(xyz, nrm, idx);
    wdiff_k<<<(64 * 3 + 255) / 256, 256>>>(ec1_w, 3, 64, wq);
    run_sgemm(xyz, 3, ec1_w, 6, 0, P, 64, BN_, 3, 64, 0, nullptr, nullptr, nullptr, 0);
    run_sgemm(xyz, 3, wq,    3, 0, Q, 64, BN_, 3, 64, 0, nullptr, nullptr, nullptr, 0);
    edge_max_k<<<BN_, 64>>>(P, Q, idx, ec1_s, ec1_t, xcat, 64, 0);

    // ---------- layer 2 (C=64, O=64: fused HMMA dist+topk, fp32 P/Q) ------
    {
        const float* X = xcat;  // lda 512
        norms_k<<<(BN_ + 255) / 256, 256>>>(X, 512, 64, nrm, BN_);
        hdist_topk_k<<<dgrid, 256, HD_SMEM>>>(X, 512, (long)N * 512, nrm, 64, idx);
        wdiff_k<<<(64 * 64 + 255) / 256, 256>>>(ec2_w, 64, 64, wq);
        run_sgemm(X, 512, ec2_w, 128, 0, P, 64, BN_, 64, 64, 0, nullptr, nullptr, nullptr, 0);
        run_sgemm(X, 512, wq,    64,  0, Q, 64, BN_, 64, 64, 0, nullptr, nullptr, nullptr, 0);
        edge_max_k<<<BN_, 64>>>(P, Q, idx, ec2_s, ec2_t, xcat, 64, 64);
    }

    // ---------- layer 3 (C=64, O=128) ----------
    {
        const float* X = xcat + 64;
        norms_k<<<(BN_ + 255) / 256, 256>>>(X, 512, 64, nrm, BN_);
        hdist_topk_k<<<dgrid, 256, HD_SMEM>>>(X, 512, (long)N * 512, nrm, 64, idx);
        wdiff_k<<<(128 * 64 + 255) / 256, 256>>>(ec3_w, 64, 128, wq);
        run_tc(X, 512, 0, ec3_w, 128, 0, P, 128, 0, BN_, 64, 128, 1, 0,
               nullptr, nullptr, nullptr, 0, 0);
        run_tc(X, 512, 0, wq, 64, 0, Q, 128, 0, BN_, 64, 128, 1, 0,
               nullptr, nullptr, nullptr, 0, 0);
        edge_max_k<<<BN_, 128>>>(P, Q, idx, ec3_s, ec3_t, xcat, 128, 128);
    }

    // ---------- layer 4 (C=128, O=256) ----------
    {
        const float* X = xcat + 128;
        norms_k<<<(BN_ + 255) / 256, 256>>>(X, 512, 128, nrm, BN_);
        hdist_topk_k<<<dgrid, 256, HD_SMEM>>>(X, 512, (long)N * 512, nrm, 128, idx);
        wdiff_k<<<(256 * 128 + 255) / 256, 256>>>(ec4_w, 128, 256, wq);
        run_tc(X, 512, 0, ec4_w, 256, 0, P, 256, 0, BN_, 128, 256, 1, 0,
               nullptr, nullptr, nullptr, 0, 0);
        run_tc(X, 512, 0, wq, 128, 0, Q, 256, 0, BN_, 128, 256, 1, 0,
               nullptr, nullptr, nullptr, 0, 0);
        edge_max_k<<<BN_, 256>>>(P, Q, idx, ec4_s, ec4_t, xcat, 256, 256);
    }

    // fuse: 512 -> 512 (HMMA)
    run_tc(xcat, 512, 0, fuse_w, 512, 0, loc, 512, 0, BN_, 512, 512, 1, 1,
           fuse_s, fuse_t, nullptr, 0, 0);
    // emb: 512 -> 1024 (HMMA), then global max over N
    run_tc(loc, 512, 0, emb_w, 512, 0, emb, 1024, 0, BN_, 512, 1024, 1, 1,
           emb_s, emb_t, nullptr, 0, 0);
    gmax_k<<<dim3(B, 4), 256>>>(emb, glob);
    // gb[b,o] = glob[b] @ h1_w[o, 512:1536]  (tiny: fp32)
    run_sgemm(glob, 1024, h1_w, 1536, 512, gb, 256, B, 1024, 256, 0,
              nullptr, nullptr, nullptr, 0);
    // h1 = lrelu((loc @ h1_w[:, :512]^T + gb[b]) * s + t)  (HMMA, mode 3)
    run_tc(loc, 512, 0, h1_w, 1536, 0, h1, 256, 0, BN_, 512, 256, 1, 3,
           h1_s, h1_t, gb, 0, N);
    // h2 (HMMA)
    run_tc(h1, 256, 0, h2_w, 256, 0, h2, 256, 0, BN_, 256, 256, 1, 1,
           h2_s, h2_t, nullptr, 0, 0);
    // logits = h2 @ h3_w^T + b (O=13: fp32)
    run_sgemm(h2, 256, h3_w, 256, 0, out, 13, BN_, 256, 13, 2,
              h3_b, nullptr, nullptr, 0);
}